// round 14
// baseline (speedup 1.0000x reference)
#include <cuda_runtime.h>
#include <cuda_fp16.h>
#include <math.h>
#include <cstdint>

#define Bsz   64
#define Ntok  197
#define EMB   768
#define NH    12
#define LAH   16
#define HID   3072
#define MTOT  (Bsz*Ntok)          // 12608

// ---------------- scratch (device globals; no allocations allowed) ----------
__device__ float  d_fusion[Bsz*LAH*49];
__device__ float  d_x1 [MTOT*EMB];
__device__ __half hd_ln [MTOT*EMB];
__device__ __half hd_qkv[MTOT*3*EMB];
__device__ __half hd_att[MTOT*EMB];
__device__ __half hd_h  [MTOT*HID];
__device__ __half hd_wq [3*EMB*EMB];
__device__ __half hd_wp [EMB*EMB];
__device__ __half hd_w1 [HID*EMB];
__device__ __half hd_w2 [EMB*HID];

// ---------------- helpers ----------------------------------------------------
__device__ __forceinline__ uint32_t smem_u32(const void* p){
    uint32_t a;
    asm("{ .reg .u64 t; cvta.to.shared.u64 t, %1; cvt.u32.u64 %0, t; }" : "=r"(a) : "l"(p));
    return a;
}

// tanh-form GELU via one __expf: g = v * sigmoid(2*0.7978845608*(v+0.044715 v^3))
__device__ __forceinline__ float gelu_fast(float v){
    float y = 1.5957691216057308f * (v + 0.044715f * v * v * v);  // 2*sqrt(2/pi)*(...)
    return v / (1.f + __expf(-y));
}

#define LDSM4(r0,r1,r2,r3,addr) \
    asm volatile("ldmatrix.sync.aligned.m8n8.x4.shared.b16 {%0,%1,%2,%3}, [%4];" \
        : "=r"(r0), "=r"(r1), "=r"(r2), "=r"(r3) : "r"(addr))

#define LDSM4T(r0,r1,r2,r3,addr) \
    asm volatile("ldmatrix.sync.aligned.m8n8.x4.trans.shared.b16 {%0,%1,%2,%3}, [%4];" \
        : "=r"(r0), "=r"(r1), "=r"(r2), "=r"(r3) : "r"(addr))

#define MMA16(dd, a0,a1,a2,a3, b0,b1) \
    asm volatile("mma.sync.aligned.m16n8k16.row.col.f32.f16.f16.f32 " \
        "{%0,%1,%2,%3}, {%4,%5,%6,%7}, {%8,%9}, {%0,%1,%2,%3};" \
        : "+f"((dd)[0]), "+f"((dd)[1]), "+f"((dd)[2]), "+f"((dd)[3]) \
        : "r"(a0), "r"(a1), "r"(a2), "r"(a3), "r"(b0), "r"(b1))

// ---------------- fp16 mma.sync GEMM ----------------------------------------
// C[M,N] = A[M,K] @ B[N,K]^T + bias (+GELU/+residual). CTA tile 128x128x64.
// 8 warps (256 thr), warp tile 64x32. 3 stages, 110.6KB smem -> 2 CTAs/SM.
// EPI: 0=bias, 1=bias+GELU, 2=bias+residual. OUTH: write half, else float.
#define PITCH_H 72
#define STAGE_BYTES (2*128*PITCH_H*2)        // 36864
#define NSTAGE 3
#define GEMM_SMEM (NSTAGE*STAGE_BYTES)       // 110592

template<int EPI, bool OUTH>
__global__ void __launch_bounds__(256, 2) gemm_f16(
    const __half* __restrict__ A, const __half* __restrict__ B,
    const float* __restrict__ bias, const float* __restrict__ res,
    void* __restrict__ Cv, int M, int N, int K)
{
    extern __shared__ char smem_dyn[];
    uint32_t sb = smem_u32(smem_dyn);
    int tid = threadIdx.x, wid = tid>>5, lane = tid&31;
    int bm = blockIdx.y*128, bn = blockIdx.x*128;
    int nc = K >> 6;                         // 64-wide K chunks

    const __half* gAr = A + (size_t)bm*K;
    const __half* gBr = B + (size_t)bn*K;

    int lrow = lane & 15;                    // ldmatrix row within 16
    int lcolh = (lane>>4)*8;                 // 8-half col offset
    int wm = (wid&1)*64, wn = (wid>>1)*32;

    float d[4][4][4];
    #pragma unroll
    for (int mi=0;mi<4;mi++)
        #pragma unroll
        for (int ni=0;ni<4;ni++)
            #pragma unroll
            for (int q=0;q<4;q++) d[mi][ni][q]=0.f;

    #define LOAD_CHUNK(s, c) do { \
        uint32_t aB = sb + (s)*STAGE_BYTES; \
        uint32_t bB = aB + 128*PITCH_H*2; \
        const __half* gA = gAr + (c)*64; \
        const __half* gB = gBr + (c)*64; \
        _Pragma("unroll") \
        for (int i=0;i<4;i++){ \
            int idx = tid + i*256; \
            int row = idx>>3, seg = idx&7; \
            uint32_t off = (uint32_t)(row*PITCH_H + seg*8)*2u; \
            int sz = (bm+row) < M ? 16 : 0; \
            asm volatile("cp.async.cg.shared.global [%0],[%1],16,%2;" \
                :: "r"(aB + off), "l"(gA + (size_t)row*K + seg*8), "r"(sz)); \
            asm volatile("cp.async.cg.shared.global [%0],[%1],16;" \
                :: "r"(bB + off), "l"(gB + (size_t)row*K + seg*8)); \
        } \
        asm volatile("cp.async.commit_group;"); } while(0)

    LOAD_CHUNK(0,0);
    LOAD_CHUNK(1,1);

    for (int c=0; c<nc; c++){
        int s = c % NSTAGE;
        asm volatile("cp.async.wait_group 1;");
        __syncthreads();
        if (c+2 < nc) LOAD_CHUNK((c+2)%NSTAGE, c+2);
        else asm volatile("cp.async.commit_group;");

        uint32_t sA = sb + s*STAGE_BYTES + (uint32_t)((wm+lrow)*PITCH_H + lcolh)*2u;
        uint32_t sB = sb + s*STAGE_BYTES + 128*PITCH_H*2 + (uint32_t)((wn+lrow)*PITCH_H + lcolh)*2u;
        #pragma unroll
        for (int kk=0;kk<4;kk++){
            uint32_t koff = kk*32;           // 16 halves
            uint32_t a[4][4];
            #pragma unroll
            for (int mi=0;mi<4;mi++)
                LDSM4(a[mi][0],a[mi][1],a[mi][2],a[mi][3], sA + mi*16*PITCH_H*2 + koff);
            uint32_t b[2][4];
            #pragma unroll
            for (int nj=0;nj<2;nj++)
                LDSM4(b[nj][0],b[nj][1],b[nj][2],b[nj][3], sB + nj*16*PITCH_H*2 + koff);
            #pragma unroll
            for (int mi=0;mi<4;mi++)
                #pragma unroll
                for (int ni=0;ni<4;ni++){
                    int nj = ni>>1, pr = ni&1;
                    MMA16(d[mi][ni], a[mi][0],a[mi][1],a[mi][2],a[mi][3],
                          b[nj][pr], b[nj][pr+2]);
                }
        }
    }

    __half* Ch = (__half*)Cv;
    float*  Cf = (float*)Cv;
    int rb = bm + wm + (lane>>2);
    int cb = bn + wn + (lane&3)*2;
    #pragma unroll
    for (int mi=0;mi<4;mi++){
        #pragma unroll
        for (int half=0; half<2; half++){
            int r = rb + mi*16 + half*8;
            if (r >= M) continue;
            const float* Rrow = (EPI==2) ? (res + (size_t)r*N) : (const float*)0;
            #pragma unroll
            for (int ni=0;ni<4;ni++){
                int cc = cb + ni*8;
                float v0 = d[mi][ni][half*2+0] + bias[cc];
                float v1 = d[mi][ni][half*2+1] + bias[cc+1];
                if (EPI==1){
                    v0 = gelu_fast(v0);
                    v1 = gelu_fast(v1);
                }
                if (EPI==2){ v0 += Rrow[cc]; v1 += Rrow[cc+1]; }
                if (OUTH)
                    *(__half2*)(Ch + (size_t)r*N + cc) = __floats2half2_rn(v0, v1);
                else
                    *(float2*)(Cf + (size_t)r*N + cc) = make_float2(v0, v1);
            }
        }
    }
}

// ---------------- fused weight float->half conversion ------------------------
#define CVT_N0 (3*EMB*EMB/4)
#define CVT_N1 (CVT_N0 + EMB*EMB/4)
#define CVT_N2 (CVT_N1 + HID*EMB/4)
#define CVT_N3 (CVT_N2 + EMB*HID/4)          // 1769472 float4 groups
__global__ void __launch_bounds__(256) cvt_all_kernel(
    const float* __restrict__ s0, __half* __restrict__ o0,
    const float* __restrict__ s1, __half* __restrict__ o1,
    const float* __restrict__ s2, __half* __restrict__ o2,
    const float* __restrict__ s3, __half* __restrict__ o3)
{
    int i = blockIdx.x*256 + threadIdx.x;
    const float4* src; __half2* dst; int off;
    if      (i < CVT_N0){ src=(const float4*)s0; dst=(__half2*)o0; off=i; }
    else if (i < CVT_N1){ src=(const float4*)s1; dst=(__half2*)o1; off=i-CVT_N0; }
    else if (i < CVT_N2){ src=(const float4*)s2; dst=(__half2*)o2; off=i-CVT_N1; }
    else                { src=(const float4*)s3; dst=(__half2*)o3; off=i-CVT_N2; }
    float4 v = src[off];
    dst[off*2+0] = __floats2half2_rn(v.x, v.y);
    dst[off*2+1] = __floats2half2_rn(v.z, v.w);
}

// ---------------- utils -----------------------------------------------------
__device__ __forceinline__ float blockReduceSum(float v, float* sh) {
    int lane = threadIdx.x & 31, w = threadIdx.x >> 5;
    #pragma unroll
    for (int o = 16; o > 0; o >>= 1) v += __shfl_xor_sync(0xffffffffu, v, o);
    if (lane == 0) sh[w] = v;
    __syncthreads();
    if (w == 0) {
        v = (lane < 8) ? sh[lane] : 0.f;
        #pragma unroll
        for (int o = 4; o > 0; o >>= 1) v += __shfl_xor_sync(0xffffffffu, v, o);
        if (lane == 0) sh[0] = v;
    }
    __syncthreads();
    float r = sh[0];
    __syncthreads();
    return r;
}

__device__ __forceinline__ void lin7(int o, int& i0, int& i1, float& w0, float& w1) {
    int k = o >> 1;
    if (o & 1) { i0 = k; i1 = (k + 1 < 7) ? k + 1 : 6; w0 = 0.75f; w1 = 0.25f; }
    else       { i0 = (k - 1 >= 0) ? k - 1 : 0; i1 = k; w0 = 0.25f; w1 = 0.75f; }
}

// ---------------- LA pooling + channel MLP + fusion --------------------------
__global__ void __launch_bounds__(256) la_pool_kernel(
    const float* __restrict__ x,
    const float* __restrict__ f1_w, const float* __restrict__ f1_b,
    const float* __restrict__ f2_w, const float* __restrict__ f2_b,
    const float* __restrict__ v_w,  const float* __restrict__ v_b,
    float* __restrict__ fusion)
{
    int pw = blockIdx.x, ph = blockIdx.y, b = blockIdx.z;
    __shared__ float s_mean[LAH], s_max[LAH];
    int warp = threadIdx.x >> 5, lane = threadIdx.x & 31;

    for (int lh = warp; lh < LAH; lh += 8) {
        float sum = 0.f, mx = -1e30f;
        #pragma unroll
        for (int t = 0; t < 6; t++) {
            int idx = lane + 32 * t;
            int g  = idx % 48;
            int sp = idx / 48;
            int h = ph * 2 + (sp >> 1);
            int w = pw * 2 + (sp & 1);
            float v = x[((size_t)b * Ntok + 1 + h * 14 + w) * EMB + lh * 48 + g];
            sum += v; mx = fmaxf(mx, v);
        }
        #pragma unroll
        for (int o = 16; o > 0; o >>= 1) {
            sum += __shfl_xor_sync(0xffffffffu, sum, o);
            mx   = fmaxf(mx, __shfl_xor_sync(0xffffffffu, mx, o));
        }
        if (lane == 0) { s_mean[lh] = sum * (1.f / 192.f); s_max[lh] = mx; }
    }
    __syncthreads();

    if (threadIdx.x < LAH) {
        float hm = f1_b[0], hx = f1_b[0];
        #pragma unroll
        for (int lh = 0; lh < LAH; lh++) {
            hm = fmaf(s_mean[lh], f1_w[lh], hm);
            hx = fmaf(s_max[lh],  f1_w[lh], hx);
        }
        hm = fmaxf(hm, 0.f); hx = fmaxf(hx, 0.f);
        int lh = threadIdx.x;
        float m  = hm * f2_w[lh] + f2_b[lh];
        float mx = hx * f2_w[lh] + f2_b[lh];
        fusion[((size_t)b * LAH + lh) * 49 + ph * 7 + pw] =
            v_w[0] * m + v_w[1] * mx + v_b[0];
    }
}

// ---------------- LayerNorm (gate-folded variant), half output ---------------
template<bool GATE>
__global__ void __launch_bounds__(256) ln_kernel(
    const float* __restrict__ x, const float* __restrict__ fusion,
    const float* __restrict__ gamma, const float* __restrict__ beta,
    __half* __restrict__ out)
{
    int t = blockIdx.x;
    int b = t / Ntok, n = t % Ntok;
    __shared__ float s_gate[LAH];
    __shared__ float s_red[8];

    if (GATE) {
        if (threadIdx.x < LAH) {
            float gv = 1.f;
            if (n > 0) {
                int hw = n - 1, oh = hw / 14, ow = hw % 14;
                int h0, h1, w0, w1; float ah0, ah1, aw0, aw1;
                lin7(oh, h0, h1, ah0, ah1);
                lin7(ow, w0, w1, aw0, aw1);
                const float* fp = fusion + ((size_t)b * LAH + threadIdx.x) * 49;
                float val = ah0 * (aw0 * fp[h0 * 7 + w0] + aw1 * fp[h0 * 7 + w1])
                          + ah1 * (aw0 * fp[h1 * 7 + w0] + aw1 * fp[h1 * 7 + w1]);
                gv = 1.f + 1.f / (1.f + __expf(-val));
            }
            s_gate[threadIdx.x] = gv;
        }
        __syncthreads();
    }

    const float* xp = x + (size_t)t * EMB;
    float v[3];
    float sum = 0.f;
    #pragma unroll
    for (int r = 0; r < 3; r++) {
        int c = threadIdx.x + 256 * r;
        float val = xp[c];
        if (GATE) val *= s_gate[c / 48];
        v[r] = val; sum += val;
    }
    sum = blockReduceSum(sum, s_red);
    float mean = sum * (1.f / (float)EMB);
    float vs = 0.f;
    #pragma unroll
    for (int r = 0; r < 3; r++) { float d = v[r] - mean; vs += d * d; }
    vs = blockReduceSum(vs, s_red);
    float inv = rsqrtf(vs * (1.f / (float)EMB) + 1e-5f);
    __half* op = out + (size_t)t * EMB;
    #pragma unroll
    for (int r = 0; r < 3; r++) {
        int c = threadIdx.x + 256 * r;
        op[c] = __float2half_rn((v[r] - mean) * inv * gamma[c] + beta[c]);
    }
}

// ---------------- fp16 tensor-core attention ---------------------------------
// grid (head=12, batch=64); 256 threads; 4 q-tiles per CTA; register softmax.
// V kept row-major, O-phase uses ldmatrix.trans (no explicit transpose).
// SMEM (bytes): K[224][72]h=32256, Q[64][72]h=9216, V[224][72]h=32256,
//               P[64][232]h=29696, red 1024  -> total 104448 (2 CTA/SM)
#define AT_K 0
#define AT_Q 32256
#define AT_V 41472
#define AT_P 73728
#define AT_R 103424
#define ATTN_SMEM (103424 + 1024)
#define VPITCH 232

__global__ void __launch_bounds__(256, 2) attn_mma(
    const __half* __restrict__ qkv, __half* __restrict__ o)
{
    extern __shared__ char smc[];
    uint32_t sbase = smem_u32(smc);
    uint32_t sK = sbase + AT_K;
    uint32_t sQ = sbase + AT_Q;
    uint32_t sV = sbase + AT_V;
    uint32_t sP = sbase + AT_P;
    __half* Pp = (__half*)(smc + AT_P);
    float* redm = (float*)(smc + AT_R);      // [2][64]
    float* reds = redm + 128;                // [2][64]

    int h = blockIdx.x, b = blockIdx.y;
    int tid = threadIdx.x, wid = tid>>5, lane = tid&31;
    size_t base = (size_t)b * Ntok * 2304 + (size_t)h * 64;

    #define LOAD_Q(qt) do { \
        _Pragma("unroll") \
        for (int i=0;i<2;i++){ \
            int idx = tid + i*256; \
            int row = idx >> 3, seg = idx & 7; \
            int tok = (qt)*64 + row; \
            int sz = (tok < Ntok) ? 16 : 0; \
            asm volatile("cp.async.cg.shared.global [%0],[%1],16,%2;" \
                :: "r"(sQ + (uint32_t)(row*PITCH_H + seg*8)*2u), \
                   "l"(qkv + base + (size_t)tok*2304 + seg*8), "r"(sz)); \
        } \
        asm volatile("cp.async.commit_group;"); } while(0)

    // K and V: 224 rows x 8 segs of 16B (rows >= Ntok zero-filled)
    #pragma unroll
    for (int i=0;i<7;i++){
        int idx = tid + i*256;
        int row = idx >> 3, seg = idx & 7;
        int sz = (row < Ntok) ? 16 : 0;
        asm volatile("cp.async.cg.shared.global [%0],[%1],16,%2;"
            :: "r"(sK + (uint32_t)(row*PITCH_H + seg*8)*2u),
               "l"(qkv + base + (size_t)row*2304 + 768 + seg*8), "r"(sz));
        asm volatile("cp.async.cg.shared.global [%0],[%1],16,%2;"
            :: "r"(sV + (uint32_t)(row*PITCH_H + seg*8)*2u),
               "l"(qkv + base + (size_t)row*2304 + 1536 + seg*8), "r"(sz));
    }
    LOAD_Q(0);   // commits K,V,Q as one group
    asm volatile("cp.async.wait_group 0;");
    __syncthreads();

    int lrow = lane & 15;
    int lcolh = (lane>>4)*8;
    int mt = wid & 3, nh = wid >> 2;
    int r1 = mt*16 + (lane>>2);              // fragment row (and +8)
    int cbase = nh*112 + (lane&3)*2;

    for (int qt=0; qt<4; qt++){
        if (qt > 0){
            asm volatile("cp.async.wait_group 0;");
            __syncthreads();
        }
        // ---- S = Q @ K^T : warp (mt,nh) -> rows mt*16+16, cols nh*112+112
        float sacc[14][4];
        #pragma unroll
        for (int t=0;t<14;t++)
            #pragma unroll
            for (int q=0;q<4;q++) sacc[t][q]=0.f;
        #pragma unroll
        for (int kk=0;kk<4;kk++){
            uint32_t koff = kk*32;
            uint32_t a0,a1,a2,a3;
            LDSM4(a0,a1,a2,a3, sQ + (uint32_t)((mt*16+lrow)*PITCH_H + lcolh)*2u + koff);
            #pragma unroll
            for (int njp=0;njp<7;njp++){
                uint32_t b0,b1,b2,b3;
                LDSM4(b0,b1,b2,b3,
                    sK + (uint32_t)((nh*112 + njp*16 + lrow)*PITCH_H + lcolh)*2u + koff);
                MMA16(sacc[njp*2+0], a0,a1,a2,a3, b0, b2);
                MMA16(sacc[njp*2+1], a0,a1,a2,a3, b1, b3);
            }
        }
        // ---- softmax: local max/sum, ONE cross-warp exchange, corr factor
        float mx1 = -1e30f, mx2 = -1e30f;
        #pragma unroll
        for (int t=0;t<14;t++){
            #pragma unroll
            for (int j=0;j<2;j++){
                int c = cbase + t*8 + j;
                float v1 = (c < Ntok) ? sacc[t][j]*0.125f   : -1e30f;
                float v2 = (c < Ntok) ? sacc[t][2+j]*0.125f : -1e30f;
                sacc[t][j] = v1; sacc[t][2+j] = v2;
                mx1 = fmaxf(mx1, v1); mx2 = fmaxf(mx2, v2);
            }
        }
        #pragma unroll
        for (int off=1; off<4; off<<=1){
            mx1 = fmaxf(mx1, __shfl_xor_sync(0xffffffffu, mx1, off));
            mx2 = fmaxf(mx2, __shfl_xor_sync(0xffffffffu, mx2, off));
        }
        float s1 = 0.f, s2 = 0.f;
        #pragma unroll
        for (int t=0;t<14;t++){
            #pragma unroll
            for (int j=0;j<2;j++){
                float e1 = __expf(sacc[t][j]   - mx1);
                float e2 = __expf(sacc[t][2+j] - mx2);
                sacc[t][j] = e1; sacc[t][2+j] = e2;
                s1 += e1; s2 += e2;
            }
        }
        #pragma unroll
        for (int off=1; off<4; off<<=1){
            s1 += __shfl_xor_sync(0xffffffffu, s1, off);
            s2 += __shfl_xor_sync(0xffffffffu, s2, off);
        }
        if ((lane&3)==0){
            redm[nh*64 + r1]   = mx1; redm[nh*64 + r1+8] = mx2;
            reds[nh*64 + r1]   = s1;  reds[nh*64 + r1+8] = s2;
        }
        __syncthreads();
        float mA1 = redm[r1],   mB1 = redm[64+r1];
        float mg1 = fmaxf(mA1, mB1);
        float den1 = reds[r1]*__expf(mA1-mg1) + reds[64+r1]*__expf(mB1-mg1);
        float corr1 = __expf(mx1 - mg1) / den1;
        float mA2 = redm[r1+8], mB2 = redm[64+r1+8];
        float mg2 = fmaxf(mA2, mB2);
        float den2 = reds[r1+8]*__expf(mA2-mg2) + reds[64+r1+8]*__expf(mB2-mg2);
        float corr2 = __expf(mx2 - mg2) / den2;

        // prefetch next Q (all warps past S-phase after the sync above)
        if (qt < 3) LOAD_Q(qt+1);

        #pragma unroll
        for (int t=0;t<14;t++){
            int c = cbase + t*8;
            *(__half2*)&Pp[r1*VPITCH + c]
                = __floats2half2_rn(sacc[t][0]*corr1, sacc[t][1]*corr1);
            *(__half2*)&Pp[(r1+8)*VPITCH + c]
                = __floats2half2_rn(sacc[t][2]*corr2, sacc[t][3]*corr2);
        }
        __syncthreads();

        // ---- O = P @ V : warp (mt,nh) -> rows mt*16+16, cols nh*32+32
        // B operand from row-major V via ldmatrix.trans
        float oacc[4][4];
        #pragma unroll
        for (int t=0;t<4;t++)
            #pragma unroll
            for (int q=0;q<4;q++) oacc[t][q]=0.f;
        #pragma unroll
        for (int k16=0;k16<14;k16++){
            uint32_t a0,a1,a2,a3;
            LDSM4(a0,a1,a2,a3, sP + (uint32_t)((mt*16+lrow)*VPITCH + lcolh)*2u + k16*32);
            #pragma unroll
            for (int nj=0;nj<2;nj++){
                uint32_t b0,b1,b2,b3;
                LDSM4T(b0,b1,b2,b3,
                    sV + (uint32_t)((k16*16 + lrow)*PITCH_H + nh*32 + nj*16 + lcolh)*2u);
                MMA16(oacc[nj*2+0], a0,a1,a2,a3, b0, b1);
                MMA16(oacc[nj*2+1], a0,a1,a2,a3, b2, b3);
            }
        }
        #pragma unroll
        for (int half=0; half<2; half++){
            int tok = qt*64 + r1 + half*8;
            if (tok < Ntok){
                __half* op = o + ((size_t)b*Ntok + tok)*EMB + h*64 + nh*32 + (lane&3)*2;
                #pragma unroll
                for (int t=0;t<4;t++)
                    *(__half2*)(op + t*8)
                        = __floats2half2_rn(oacc[t][half*2], oacc[t][half*2+1]);
            }
        }
    }
}

// ---------------- launch -----------------------------------------------------
extern "C" void kernel_launch(void* const* d_in, const int* in_sizes, int n_in,
                              void* d_out, int out_size)
{
    const float* x       = (const float*)d_in[0];
    const float* norm1_g = (const float*)d_in[1];
    const float* norm1_b = (const float*)d_in[2];
    const float* qkv_w   = (const float*)d_in[3];
    const float* qkv_b   = (const float*)d_in[4];
    const float* proj_w  = (const float*)d_in[5];
    const float* proj_b  = (const float*)d_in[6];
    const float* norm2_g = (const float*)d_in[7];
    const float* norm2_b = (const float*)d_in[8];
    const float* fc1_w   = (const float*)d_in[9];
    const float* fc1_b   = (const float*)d_in[10];
    const float* fc2_w   = (const float*)d_in[11];
    const float* fc2_b   = (const float*)d_in[12];
    const float* f1_w    = (const float*)d_in[13];
    const float* f1_b    = (const float*)d_in[14];
    const float* f2_w    = (const float*)d_in[15];
    const float* f2_b    = (const float*)d_in[16];
    const float* v_w     = (const float*)d_in[17];
    const float* v_b     = (const float*)d_in[18];
    float* out = (float*)d_out;

    float *fusion, *x1;
    __half *ln, *qkvb, *attno, *hbuf, *wq, *wp, *w1, *w2;
    cudaGetSymbolAddress((void**)&fusion, d_fusion);
    cudaGetSymbolAddress((void**)&x1,     d_x1);
    cudaGetSymbolAddress((void**)&ln,     hd_ln);
    cudaGetSymbolAddress((void**)&qkvb,   hd_qkv);
    cudaGetSymbolAddress((void**)&attno,  hd_att);
    cudaGetSymbolAddress((void**)&hbuf,   hd_h);
    cudaGetSymbolAddress((void**)&wq,     hd_wq);
    cudaGetSymbolAddress((void**)&wp,     hd_wp);
    cudaGetSymbolAddress((void**)&w1,     hd_w1);
    cudaGetSymbolAddress((void**)&w2,     hd_w2);

    cudaFuncSetAttribute(attn_mma, cudaFuncAttributeMaxDynamicSharedMemorySize, ATTN_SMEM);
    cudaFuncSetAttribute(gemm_f16<0,true >, cudaFuncAttributeMaxDynamicSharedMemorySize, GEMM_SMEM);
    cudaFuncSetAttribute(gemm_f16<1,true >, cudaFuncAttributeMaxDynamicSharedMemorySize, GEMM_SMEM);
    cudaFuncSetAttribute(gemm_f16<2,false>, cudaFuncAttributeMaxDynamicSharedMemorySize, GEMM_SMEM);

    // weights -> half copies (single fused launch)
    cvt_all_kernel<<<CVT_N3/256, 256>>>(qkv_w, wq, proj_w, wp, fc1_w, w1, fc2_w, w2);

    int mTiles = (MTOT + 127) / 128;   // 99

    // 1. LA pooling
    la_pool_kernel<<<dim3(7, 7, Bsz), 256>>>(x, f1_w, f1_b, f2_w, f2_b, v_w, v_b, fusion);
    // 2. LN1 (gate folded) -> half
    ln_kernel<true><<<MTOT, 256>>>(x, fusion, norm1_g, norm1_b, ln);
    // 3. QKV GEMM (fp16 tensor) -> half
    gemm_f16<0,true><<<dim3(2304/128, mTiles), 256, GEMM_SMEM>>>(
        ln, wq, qkv_b, nullptr, qkvb, MTOT, 2304, EMB);
    // 4. fp16 tensor-core attention -> half
    attn_mma<<<dim3(NH, Bsz), 256, ATTN_SMEM>>>(qkvb, attno);
    // 5. proj GEMM + residual(x) -> float x1
    gemm_f16<2,false><<<dim3(EMB/128, mTiles), 256, GEMM_SMEM>>>(
        attno, wp, proj_b, x, x1, MTOT, EMB, EMB);
    // 6. LN2 -> half
    ln_kernel<false><<<MTOT, 256>>>(x1, nullptr, norm2_g, norm2_b, ln);
    // 7. fc1 GEMM + fast GELU -> half
    gemm_f16<1,true><<<dim3(HID/128, mTiles), 256, GEMM_SMEM>>>(
        ln, w1, fc1_b, nullptr, hbuf, MTOT, HID, EMB);
    // 8. fc2 GEMM + residual(x1) -> float out
    gemm_f16<2,false><<<dim3(EMB/128, mTiles), 256, GEMM_SMEM>>>(
        hbuf, w2, fc2_b, x1, out, MTOT, EMB, HID);
}

// round 15
// speedup vs baseline: 1.0032x; 1.0032x over previous
#include <cuda_runtime.h>
#include <cuda_fp16.h>
#include <math.h>
#include <cstdint>

#define Bsz   64
#define Ntok  197
#define EMB   768
#define NH    12
#define LAH   16
#define HID   3072
#define MTOT  (Bsz*Ntok)          // 12608

// ---------------- scratch (device globals; no allocations allowed) ----------
__device__ float  d_fusion[Bsz*LAH*49];
__device__ float  d_x1 [MTOT*EMB];
__device__ __half hd_ln [MTOT*EMB];
__device__ __half hd_qkv[MTOT*3*EMB];
__device__ __half hd_att[MTOT*EMB];
__device__ __half hd_h  [MTOT*HID];
__device__ __half hd_wq [3*EMB*EMB];
__device__ __half hd_wp [EMB*EMB];
__device__ __half hd_w1 [HID*EMB];
__device__ __half hd_w2 [EMB*HID];

// ---------------- helpers ----------------------------------------------------
__device__ __forceinline__ uint32_t smem_u32(const void* p){
    uint32_t a;
    asm("{ .reg .u64 t; cvta.to.shared.u64 t, %1; cvt.u32.u64 %0, t; }" : "=r"(a) : "l"(p));
    return a;
}

#define LDSM4(r0,r1,r2,r3,addr) \
    asm volatile("ldmatrix.sync.aligned.m8n8.x4.shared.b16 {%0,%1,%2,%3}, [%4];" \
        : "=r"(r0), "=r"(r1), "=r"(r2), "=r"(r3) : "r"(addr))

#define LDSM4T(r0,r1,r2,r3,addr) \
    asm volatile("ldmatrix.sync.aligned.m8n8.x4.trans.shared.b16 {%0,%1,%2,%3}, [%4];" \
        : "=r"(r0), "=r"(r1), "=r"(r2), "=r"(r3) : "r"(addr))

#define MMA16(dd, a0,a1,a2,a3, b0,b1) \
    asm volatile("mma.sync.aligned.m16n8k16.row.col.f32.f16.f16.f32 " \
        "{%0,%1,%2,%3}, {%4,%5,%6,%7}, {%8,%9}, {%0,%1,%2,%3};" \
        : "+f"((dd)[0]), "+f"((dd)[1]), "+f"((dd)[2]), "+f"((dd)[3]) \
        : "r"(a0), "r"(a1), "r"(a2), "r"(a3), "r"(b0), "r"(b1))

// ---------------- fp16 mma.sync GEMM ----------------------------------------
// C[M,N] = A[M,K] @ B[N,K]^T + bias (+GELU/+residual). CTA tile 128x128x64.
// 8 warps (256 thr), warp tile 64x32. 3 stages, 110.6KB smem -> 2 CTAs/SM.
// EPI: 0=bias, 1=bias+GELU, 2=bias+residual. OUTH: write half, else float.
#define PITCH_H 72
#define STAGE_BYTES (2*128*PITCH_H*2)        // 36864
#define NSTAGE 3
#define GEMM_SMEM (NSTAGE*STAGE_BYTES)       // 110592

template<int EPI, bool OUTH>
__global__ void __launch_bounds__(256, 2) gemm_f16(
    const __half* __restrict__ A, const __half* __restrict__ B,
    const float* __restrict__ bias, const float* __restrict__ res,
    void* __restrict__ Cv, int M, int N, int K)
{
    extern __shared__ char smem_dyn[];
    uint32_t sb = smem_u32(smem_dyn);
    int tid = threadIdx.x, wid = tid>>5, lane = tid&31;
    int bm = blockIdx.y*128, bn = blockIdx.x*128;
    int nc = K >> 6;                         // 64-wide K chunks

    const __half* gAr = A + (size_t)bm*K;
    const __half* gBr = B + (size_t)bn*K;

    int lrow = lane & 15;                    // ldmatrix row within 16
    int lcolh = (lane>>4)*8;                 // 8-half col offset
    int wm = (wid&1)*64, wn = (wid>>1)*32;

    float d[4][4][4];
    #pragma unroll
    for (int mi=0;mi<4;mi++)
        #pragma unroll
        for (int ni=0;ni<4;ni++)
            #pragma unroll
            for (int q=0;q<4;q++) d[mi][ni][q]=0.f;

    #define LOAD_CHUNK(s, c) do { \
        uint32_t aB = sb + (s)*STAGE_BYTES; \
        uint32_t bB = aB + 128*PITCH_H*2; \
        const __half* gA = gAr + (c)*64; \
        const __half* gB = gBr + (c)*64; \
        _Pragma("unroll") \
        for (int i=0;i<4;i++){ \
            int idx = tid + i*256; \
            int row = idx>>3, seg = idx&7; \
            uint32_t off = (uint32_t)(row*PITCH_H + seg*8)*2u; \
            int sz = (bm+row) < M ? 16 : 0; \
            asm volatile("cp.async.cg.shared.global [%0],[%1],16,%2;" \
                :: "r"(aB + off), "l"(gA + (size_t)row*K + seg*8), "r"(sz)); \
            asm volatile("cp.async.cg.shared.global [%0],[%1],16;" \
                :: "r"(bB + off), "l"(gB + (size_t)row*K + seg*8)); \
        } \
        asm volatile("cp.async.commit_group;"); } while(0)

    LOAD_CHUNK(0,0);
    LOAD_CHUNK(1,1);

    for (int c=0; c<nc; c++){
        int s = c % NSTAGE;
        asm volatile("cp.async.wait_group 1;");
        __syncthreads();
        if (c+2 < nc) LOAD_CHUNK((c+2)%NSTAGE, c+2);
        else asm volatile("cp.async.commit_group;");

        uint32_t sA = sb + s*STAGE_BYTES + (uint32_t)((wm+lrow)*PITCH_H + lcolh)*2u;
        uint32_t sB = sb + s*STAGE_BYTES + 128*PITCH_H*2 + (uint32_t)((wn+lrow)*PITCH_H + lcolh)*2u;
        #pragma unroll
        for (int kk=0;kk<4;kk++){
            uint32_t koff = kk*32;           // 16 halves
            uint32_t a[4][4];
            #pragma unroll
            for (int mi=0;mi<4;mi++)
                LDSM4(a[mi][0],a[mi][1],a[mi][2],a[mi][3], sA + mi*16*PITCH_H*2 + koff);
            uint32_t b[2][4];
            #pragma unroll
            for (int nj=0;nj<2;nj++)
                LDSM4(b[nj][0],b[nj][1],b[nj][2],b[nj][3], sB + nj*16*PITCH_H*2 + koff);
            #pragma unroll
            for (int mi=0;mi<4;mi++)
                #pragma unroll
                for (int ni=0;ni<4;ni++){
                    int nj = ni>>1, pr = ni&1;
                    MMA16(d[mi][ni], a[mi][0],a[mi][1],a[mi][2],a[mi][3],
                          b[nj][pr], b[nj][pr+2]);
                }
        }
    }

    __half* Ch = (__half*)Cv;
    float*  Cf = (float*)Cv;
    int rb = bm + wm + (lane>>2);
    int cb = bn + wn + (lane&3)*2;
    #pragma unroll
    for (int mi=0;mi<4;mi++){
        #pragma unroll
        for (int half=0; half<2; half++){
            int r = rb + mi*16 + half*8;
            if (r >= M) continue;
            const float* Rrow = (EPI==2) ? (res + (size_t)r*N) : (const float*)0;
            #pragma unroll
            for (int ni=0;ni<4;ni++){
                int cc = cb + ni*8;
                float v0 = d[mi][ni][half*2+0] + bias[cc];
                float v1 = d[mi][ni][half*2+1] + bias[cc+1];
                if (EPI==1){
                    v0 = 0.5f*v0*(1.f + erff(v0*0.70710678118654752f));
                    v1 = 0.5f*v1*(1.f + erff(v1*0.70710678118654752f));
                }
                if (EPI==2){ v0 += Rrow[cc]; v1 += Rrow[cc+1]; }
                if (OUTH)
                    *(__half2*)(Ch + (size_t)r*N + cc) = __floats2half2_rn(v0, v1);
                else
                    *(float2*)(Cf + (size_t)r*N + cc) = make_float2(v0, v1);
            }
        }
    }
}

// ---------------- fused weight float->half conversion ------------------------
#define CVT_N0 (3*EMB*EMB/4)
#define CVT_N1 (CVT_N0 + EMB*EMB/4)
#define CVT_N2 (CVT_N1 + HID*EMB/4)
#define CVT_N3 (CVT_N2 + EMB*HID/4)          // 1769472 float4 groups
__global__ void __launch_bounds__(256) cvt_all_kernel(
    const float* __restrict__ s0, __half* __restrict__ o0,
    const float* __restrict__ s1, __half* __restrict__ o1,
    const float* __restrict__ s2, __half* __restrict__ o2,
    const float* __restrict__ s3, __half* __restrict__ o3)
{
    int i = blockIdx.x*256 + threadIdx.x;
    const float4* src; __half2* dst; int off;
    if      (i < CVT_N0){ src=(const float4*)s0; dst=(__half2*)o0; off=i; }
    else if (i < CVT_N1){ src=(const float4*)s1; dst=(__half2*)o1; off=i-CVT_N0; }
    else if (i < CVT_N2){ src=(const float4*)s2; dst=(__half2*)o2; off=i-CVT_N1; }
    else                { src=(const float4*)s3; dst=(__half2*)o3; off=i-CVT_N2; }
    float4 v = src[off];
    dst[off*2+0] = __floats2half2_rn(v.x, v.y);
    dst[off*2+1] = __floats2half2_rn(v.z, v.w);
}

// ---------------- utils -----------------------------------------------------
__device__ __forceinline__ float blockReduceSum(float v, float* sh) {
    int lane = threadIdx.x & 31, w = threadIdx.x >> 5;
    #pragma unroll
    for (int o = 16; o > 0; o >>= 1) v += __shfl_xor_sync(0xffffffffu, v, o);
    if (lane == 0) sh[w] = v;
    __syncthreads();
    if (w == 0) {
        v = (lane < 8) ? sh[lane] : 0.f;
        #pragma unroll
        for (int o = 4; o > 0; o >>= 1) v += __shfl_xor_sync(0xffffffffu, v, o);
        if (lane == 0) sh[0] = v;
    }
    __syncthreads();
    float r = sh[0];
    __syncthreads();
    return r;
}

__device__ __forceinline__ void lin7(int o, int& i0, int& i1, float& w0, float& w1) {
    int k = o >> 1;
    if (o & 1) { i0 = k; i1 = (k + 1 < 7) ? k + 1 : 6; w0 = 0.75f; w1 = 0.25f; }
    else       { i0 = (k - 1 >= 0) ? k - 1 : 0; i1 = k; w0 = 0.25f; w1 = 0.75f; }
}

// ---------------- LA pooling + channel MLP + fusion --------------------------
__global__ void __launch_bounds__(256) la_pool_kernel(
    const float* __restrict__ x,
    const float* __restrict__ f1_w, const float* __restrict__ f1_b,
    const float* __restrict__ f2_w, const float* __restrict__ f2_b,
    const float* __restrict__ v_w,  const float* __restrict__ v_b,
    float* __restrict__ fusion)
{
    int pw = blockIdx.x, ph = blockIdx.y, b = blockIdx.z;
    __shared__ float s_mean[LAH], s_max[LAH];
    int warp = threadIdx.x >> 5, lane = threadIdx.x & 31;

    for (int lh = warp; lh < LAH; lh += 8) {
        float sum = 0.f, mx = -1e30f;
        #pragma unroll
        for (int t = 0; t < 6; t++) {
            int idx = lane + 32 * t;
            int g  = idx % 48;
            int sp = idx / 48;
            int h = ph * 2 + (sp >> 1);
            int w = pw * 2 + (sp & 1);
            float v = x[((size_t)b * Ntok + 1 + h * 14 + w) * EMB + lh * 48 + g];
            sum += v; mx = fmaxf(mx, v);
        }
        #pragma unroll
        for (int o = 16; o > 0; o >>= 1) {
            sum += __shfl_xor_sync(0xffffffffu, sum, o);
            mx   = fmaxf(mx, __shfl_xor_sync(0xffffffffu, mx, o));
        }
        if (lane == 0) { s_mean[lh] = sum * (1.f / 192.f); s_max[lh] = mx; }
    }
    __syncthreads();

    if (threadIdx.x < LAH) {
        float hm = f1_b[0], hx = f1_b[0];
        #pragma unroll
        for (int lh = 0; lh < LAH; lh++) {
            hm = fmaf(s_mean[lh], f1_w[lh], hm);
            hx = fmaf(s_max[lh],  f1_w[lh], hx);
        }
        hm = fmaxf(hm, 0.f); hx = fmaxf(hx, 0.f);
        int lh = threadIdx.x;
        float m  = hm * f2_w[lh] + f2_b[lh];
        float mx = hx * f2_w[lh] + f2_b[lh];
        fusion[((size_t)b * LAH + lh) * 49 + ph * 7 + pw] =
            v_w[0] * m + v_w[1] * mx + v_b[0];
    }
}

// ---------------- LayerNorm (gate-folded variant), half output ---------------
template<bool GATE>
__global__ void __launch_bounds__(256) ln_kernel(
    const float* __restrict__ x, const float* __restrict__ fusion,
    const float* __restrict__ gamma, const float* __restrict__ beta,
    __half* __restrict__ out)
{
    int t = blockIdx.x;
    int b = t / Ntok, n = t % Ntok;
    __shared__ float s_gate[LAH];
    __shared__ float s_red[8];

    if (GATE) {
        if (threadIdx.x < LAH) {
            float gv = 1.f;
            if (n > 0) {
                int hw = n - 1, oh = hw / 14, ow = hw % 14;
                int h0, h1, w0, w1; float ah0, ah1, aw0, aw1;
                lin7(oh, h0, h1, ah0, ah1);
                lin7(ow, w0, w1, aw0, aw1);
                const float* fp = fusion + ((size_t)b * LAH + threadIdx.x) * 49;
                float val = ah0 * (aw0 * fp[h0 * 7 + w0] + aw1 * fp[h0 * 7 + w1])
                          + ah1 * (aw0 * fp[h1 * 7 + w0] + aw1 * fp[h1 * 7 + w1]);
                gv = 1.f + 1.f / (1.f + __expf(-val));
            }
            s_gate[threadIdx.x] = gv;
        }
        __syncthreads();
    }

    const float* xp = x + (size_t)t * EMB;
    float v[3];
    float sum = 0.f;
    #pragma unroll
    for (int r = 0; r < 3; r++) {
        int c = threadIdx.x + 256 * r;
        float val = xp[c];
        if (GATE) val *= s_gate[c / 48];
        v[r] = val; sum += val;
    }
    sum = blockReduceSum(sum, s_red);
    float mean = sum * (1.f / (float)EMB);
    float vs = 0.f;
    #pragma unroll
    for (int r = 0; r < 3; r++) { float d = v[r] - mean; vs += d * d; }
    vs = blockReduceSum(vs, s_red);
    float inv = rsqrtf(vs * (1.f / (float)EMB) + 1e-5f);
    __half* op = out + (size_t)t * EMB;
    #pragma unroll
    for (int r = 0; r < 3; r++) {
        int c = threadIdx.x + 256 * r;
        op[c] = __float2half_rn((v[r] - mean) * inv * gamma[c] + beta[c]);
    }
}

// ---------------- fp16 tensor-core attention ---------------------------------
// grid (head=12, batch=64); 256 threads; 4 q-tiles per CTA; register softmax.
// V row-major + ldmatrix.trans O-phase; V load overlapped with first S-phase;
// pairwise named barriers between P-write and O-phase (P/red are pair-local).
// SMEM (bytes): K[224][72]h=32256, Q[64][72]h=9216, V[224][72]h=32256,
//               P[64][232]h=29696, red 1024  -> total 104448 (2 CTA/SM)
#define AT_K 0
#define AT_Q 32256
#define AT_V 41472
#define AT_P 73728
#define AT_R 103424
#define ATTN_SMEM (103424 + 1024)
#define VPITCH 232

__global__ void __launch_bounds__(256, 2) attn_mma(
    const __half* __restrict__ qkv, __half* __restrict__ o)
{
    extern __shared__ char smc[];
    uint32_t sbase = smem_u32(smc);
    uint32_t sK = sbase + AT_K;
    uint32_t sQ = sbase + AT_Q;
    uint32_t sV = sbase + AT_V;
    uint32_t sP = sbase + AT_P;
    __half* Pp = (__half*)(smc + AT_P);
    float* redm = (float*)(smc + AT_R);      // [2][64]
    float* reds = redm + 128;                // [2][64]

    int h = blockIdx.x, b = blockIdx.y;
    int tid = threadIdx.x, wid = tid>>5, lane = tid&31;
    size_t base = (size_t)b * Ntok * 2304 + (size_t)h * 64;

    #define LOAD_Q(qt) do { \
        _Pragma("unroll") \
        for (int i=0;i<2;i++){ \
            int idx = tid + i*256; \
            int row = idx >> 3, seg = idx & 7; \
            int tok = (qt)*64 + row; \
            int sz = (tok < Ntok) ? 16 : 0; \
            asm volatile("cp.async.cg.shared.global [%0],[%1],16,%2;" \
                :: "r"(sQ + (uint32_t)(row*PITCH_H + seg*8)*2u), \
                   "l"(qkv + base + (size_t)tok*2304 + seg*8), "r"(sz)); \
        } \
        asm volatile("cp.async.commit_group;"); } while(0)

    // group 0: K (224 rows x 8 segs of 16B; rows >= Ntok zero-filled)
    #pragma unroll
    for (int i=0;i<7;i++){
        int idx = tid + i*256;
        int row = idx >> 3, seg = idx & 7;
        int sz = (row < Ntok) ? 16 : 0;
        asm volatile("cp.async.cg.shared.global [%0],[%1],16,%2;"
            :: "r"(sK + (uint32_t)(row*PITCH_H + seg*8)*2u),
               "l"(qkv + base + (size_t)row*2304 + 768 + seg*8), "r"(sz));
    }
    asm volatile("cp.async.commit_group;");
    // group 1: Q tile 0
    LOAD_Q(0);
    // group 2: V (overlaps with first S-phase + softmax)
    #pragma unroll
    for (int i=0;i<7;i++){
        int idx = tid + i*256;
        int row = idx >> 3, seg = idx & 7;
        int sz = (row < Ntok) ? 16 : 0;
        asm volatile("cp.async.cg.shared.global [%0],[%1],16,%2;"
            :: "r"(sV + (uint32_t)(row*PITCH_H + seg*8)*2u),
               "l"(qkv + base + (size_t)row*2304 + 1536 + seg*8), "r"(sz));
    }
    asm volatile("cp.async.commit_group;");
    asm volatile("cp.async.wait_group 1;");  // K + Q ready; V still in flight
    __syncthreads();

    int lrow = lane & 15;
    int lcolh = (lane>>4)*8;
    int mt = wid & 3, nh = wid >> 2;
    int r1 = mt*16 + (lane>>2);              // fragment row (and +8)
    int cbase = nh*112 + (lane&3)*2;

    for (int qt=0; qt<4; qt++){
        if (qt > 0){
            asm volatile("cp.async.wait_group 0;");
            __syncthreads();
        }
        // ---- S = Q @ K^T : warp (mt,nh) -> rows mt*16+16, cols nh*112+112
        float sacc[14][4];
        #pragma unroll
        for (int t=0;t<14;t++)
            #pragma unroll
            for (int q=0;q<4;q++) sacc[t][q]=0.f;
        #pragma unroll
        for (int kk=0;kk<4;kk++){
            uint32_t koff = kk*32;
            uint32_t a0,a1,a2,a3;
            LDSM4(a0,a1,a2,a3, sQ + (uint32_t)((mt*16+lrow)*PITCH_H + lcolh)*2u + koff);
            #pragma unroll
            for (int njp=0;njp<7;njp++){
                uint32_t b0,b1,b2,b3;
                LDSM4(b0,b1,b2,b3,
                    sK + (uint32_t)((nh*112 + njp*16 + lrow)*PITCH_H + lcolh)*2u + koff);
                MMA16(sacc[njp*2+0], a0,a1,a2,a3, b0, b2);
                MMA16(sacc[njp*2+1], a0,a1,a2,a3, b1, b3);
            }
        }
        // ---- softmax: local max/sum, ONE cross-warp exchange, corr factor
        float mx1 = -1e30f, mx2 = -1e30f;
        #pragma unroll
        for (int t=0;t<14;t++){
            #pragma unroll
            for (int j=0;j<2;j++){
                int c = cbase + t*8 + j;
                float v1 = (c < Ntok) ? sacc[t][j]*0.125f   : -1e30f;
                float v2 = (c < Ntok) ? sacc[t][2+j]*0.125f : -1e30f;
                sacc[t][j] = v1; sacc[t][2+j] = v2;
                mx1 = fmaxf(mx1, v1); mx2 = fmaxf(mx2, v2);
            }
        }
        #pragma unroll
        for (int off=1; off<4; off<<=1){
            mx1 = fmaxf(mx1, __shfl_xor_sync(0xffffffffu, mx1, off));
            mx2 = fmaxf(mx2, __shfl_xor_sync(0xffffffffu, mx2, off));
        }
        float s1 = 0.f, s2 = 0.f;
        #pragma unroll
        for (int t=0;t<14;t++){
            #pragma unroll
            for (int j=0;j<2;j++){
                float e1 = __expf(sacc[t][j]   - mx1);
                float e2 = __expf(sacc[t][2+j] - mx2);
                sacc[t][j] = e1; sacc[t][2+j] = e2;
                s1 += e1; s2 += e2;
            }
        }
        #pragma unroll
        for (int off=1; off<4; off<<=1){
            s1 += __shfl_xor_sync(0xffffffffu, s1, off);
            s2 += __shfl_xor_sync(0xffffffffu, s2, off);
        }
        if ((lane&3)==0){
            redm[nh*64 + r1]   = mx1; redm[nh*64 + r1+8] = mx2;
            reds[nh*64 + r1]   = s1;  reds[nh*64 + r1+8] = s2;
        }
        __syncthreads();                      // full: also guards Q prefetch below
        float mA1 = redm[r1],   mB1 = redm[64+r1];
        float mg1 = fmaxf(mA1, mB1);
        float den1 = reds[r1]*__expf(mA1-mg1) + reds[64+r1]*__expf(mB1-mg1);
        float corr1 = __expf(mx1 - mg1) / den1;
        float mA2 = redm[r1+8], mB2 = redm[64+r1+8];
        float mg2 = fmaxf(mA2, mB2);
        float den2 = reds[r1+8]*__expf(mA2-mg2) + reds[64+r1+8]*__expf(mB2-mg2);
        float corr2 = __expf(mx2 - mg2) / den2;

        // prefetch next Q (all warps past S-phase after the full sync above)
        if (qt < 3) LOAD_Q(qt+1);

        #pragma unroll
        for (int t=0;t<14;t++){
            int c = cbase + t*8;
            *(__half2*)&Pp[r1*VPITCH + c]
                = __floats2half2_rn(sacc[t][0]*corr1, sacc[t][1]*corr1);
            *(__half2*)&Pp[(r1+8)*VPITCH + c]
                = __floats2half2_rn(sacc[t][2]*corr2, sacc[t][3]*corr2);
        }
        if (qt == 0){
            // V (group 2) must be complete; allow next-Q group to stay pending.
            asm volatile("cp.async.wait_group 1;");
            __syncthreads();                  // full: V visibility across all loaders
        } else {
            // P/red are pair-local: sync only warp pair {(mt,0),(mt,1)} = 64 thr
            asm volatile("bar.sync %0, 64;" :: "r"(1 + mt) : "memory");
        }

        // ---- O = P @ V : warp (mt,nh) -> rows mt*16+16, cols nh*32+32
        // B operand from row-major V via ldmatrix.trans
        float oacc[4][4];
        #pragma unroll
        for (int t=0;t<4;t++)
            #pragma unroll
            for (int q=0;q<4;q++) oacc[t][q]=0.f;
        #pragma unroll
        for (int k16=0;k16<14;k16++){
            uint32_t a0,a1,a2,a3;
            LDSM4(a0,a1,a2,a3, sP + (uint32_t)((mt*16+lrow)*VPITCH + lcolh)*2u + k16*32);
            #pragma unroll
            for (int nj=0;nj<2;nj++){
                uint32_t b0,b1,b2,b3;
                LDSM4T(b0,b1,b2,b3,
                    sV + (uint32_t)((k16*16 + lrow)*PITCH_H + nh*32 + nj*16 + lcolh)*2u);
                MMA16(oacc[nj*2+0], a0,a1,a2,a3, b0, b1);
                MMA16(oacc[nj*2+1], a0,a1,a2,a3, b2, b3);
            }
        }
        #pragma unroll
        for (int half=0; half<2; half++){
            int tok = qt*64 + r1 + half*8;
            if (tok < Ntok){
                __half* op = o + ((size_t)b*Ntok + tok)*EMB + h*64 + nh*32 + (lane&3)*2;
                #pragma unroll
                for (int t=0;t<4;t++)
                    *(__half2*)(op + t*8)
                        = __floats2half2_rn(oacc[t][half*2], oacc[t][half*2+1]);
            }
        }
    }
}

// ---------------- launch -----------------------------------------------------
extern "C" void kernel_launch(void* const* d_in, const int* in_sizes, int n_in,
                              void* d_out, int out_size)
{
    const float* x       = (const float*)d_in[0];
    const float* norm1_g = (const float*)d_in[1];
    const float* norm1_b = (const float*)d_in[2];
    const float* qkv_w   = (const float*)d_in[3];
    const float* qkv_b   = (const float*)d_in[4];
    const float* proj_w  = (const float*)d_in[5];
    const float* proj_b  = (const float*)d_in[6];
    const float* norm2_g = (const float*)d_in[7];
    const float* norm2_b = (const float*)d_in[8];
    const float* fc1_w   = (const float*)d_in[9];
    const float* fc1_b   = (const float*)d_in[10];
    const float* fc2_w   = (const float*)d_in[11];
    const float* fc2_b   = (const float*)d_in[12];
    const float* f1_w    = (const float*)d_in[13];
    const float* f1_b    = (const float*)d_in[14];
    const float* f2_w    = (const float*)d_in[15];
    const float* f2_b    = (const float*)d_in[16];
    const float* v_w     = (const float*)d_in[17];
    const float* v_b     = (const float*)d_in[18];
    float* out = (float*)d_out;

    float *fusion, *x1;
    __half *ln, *qkvb, *attno, *hbuf, *wq, *wp, *w1, *w2;
    cudaGetSymbolAddress((void**)&fusion, d_fusion);
    cudaGetSymbolAddress((void**)&x1,     d_x1);
    cudaGetSymbolAddress((void**)&ln,     hd_ln);
    cudaGetSymbolAddress((void**)&qkvb,   hd_qkv);
    cudaGetSymbolAddress((void**)&attno,  hd_att);
    cudaGetSymbolAddress((void**)&hbuf,   hd_h);
    cudaGetSymbolAddress((void**)&wq,     hd_wq);
    cudaGetSymbolAddress((void**)&wp,     hd_wp);
    cudaGetSymbolAddress((void**)&w1,     hd_w1);
    cudaGetSymbolAddress((void**)&w2,     hd_w2);

    cudaFuncSetAttribute(attn_mma, cudaFuncAttributeMaxDynamicSharedMemorySize, ATTN_SMEM);
    cudaFuncSetAttribute(gemm_f16<0,true >, cudaFuncAttributeMaxDynamicSharedMemorySize, GEMM_SMEM);
    cudaFuncSetAttribute(gemm_f16<1,true >, cudaFuncAttributeMaxDynamicSharedMemorySize, GEMM_SMEM);
    cudaFuncSetAttribute(gemm_f16<2,false>, cudaFuncAttributeMaxDynamicSharedMemorySize, GEMM_SMEM);

    // weights -> half copies (single fused launch)
    cvt_all_kernel<<<CVT_N3/256, 256>>>(qkv_w, wq, proj_w, wp, fc1_w, w1, fc2_w, w2);

    int mTiles = (MTOT + 127) / 128;   // 99

    // 1. LA pooling
    la_pool_kernel<<<dim3(7, 7, Bsz), 256>>>(x, f1_w, f1_b, f2_w, f2_b, v_w, v_b, fusion);
    // 2. LN1 (gate folded) -> half
    ln_kernel<true><<<MTOT, 256>>>(x, fusion, norm1_g, norm1_b, ln);
    // 3. QKV GEMM (fp16 tensor) -> half
    gemm_f16<0,true><<<dim3(2304/128, mTiles), 256, GEMM_SMEM>>>(
        ln, wq, qkv_b, nullptr, qkvb, MTOT, 2304, EMB);
    // 4. fp16 tensor-core attention -> half
    attn_mma<<<dim3(NH, Bsz), 256, ATTN_SMEM>>>(qkvb, attno);
    // 5. proj GEMM + residual(x) -> float x1
    gemm_f16<2,false><<<dim3(EMB/128, mTiles), 256, GEMM_SMEM>>>(
        attno, wp, proj_b, x, x1, MTOT, EMB, EMB);
    // 6. LN2 -> half
    ln_kernel<false><<<MTOT, 256>>>(x1, nullptr, norm2_g, norm2_b, ln);
    // 7. fc1 GEMM + exact GELU -> half
    gemm_f16<1,true><<<dim3(HID/128, mTiles), 256, GEMM_SMEM>>>(
        ln, w1, fc1_b, nullptr, hbuf, MTOT, HID, EMB);
    // 8. fc2 GEMM + residual(x1) -> float out
    gemm_f16<2,false><<<dim3(EMB/128, mTiles), 256, GEMM_SMEM>>>(
        hbuf, w2, fc2_b, x1, out, MTOT, EMB, HID);
}

// round 17
// speedup vs baseline: 1.0265x; 1.0232x over previous
#include <cuda_runtime.h>
#include <cuda_fp16.h>
#include <math.h>
#include <cstdint>

#define Bsz   64
#define Ntok  197
#define EMB   768
#define NH    12
#define LAH   16
#define HID   3072
#define MTOT  (Bsz*Ntok)          // 12608

// ---------------- scratch (device globals; no allocations allowed) ----------
__device__ float  d_fusion[Bsz*LAH*49];
__device__ float  d_x1 [MTOT*EMB];
__device__ __half hd_ln [MTOT*EMB];
__device__ __half hd_qkv[MTOT*3*EMB];
__device__ __half hd_att[MTOT*EMB];
__device__ __half hd_h  [MTOT*HID];
__device__ __half hd_wq [3*EMB*EMB];
__device__ __half hd_wp [EMB*EMB];
__device__ __half hd_w1 [HID*EMB];
__device__ __half hd_w2 [EMB*HID];

// ---------------- helpers ----------------------------------------------------
__device__ __forceinline__ uint32_t smem_u32(const void* p){
    uint32_t a;
    asm("{ .reg .u64 t; cvta.to.shared.u64 t, %1; cvt.u32.u64 %0, t; }" : "=r"(a) : "l"(p));
    return a;
}

struct half2x2 { __half2 a, b; };            // 8-byte vector store

#define LDSM4(r0,r1,r2,r3,addr) \
    asm volatile("ldmatrix.sync.aligned.m8n8.x4.shared.b16 {%0,%1,%2,%3}, [%4];" \
        : "=r"(r0), "=r"(r1), "=r"(r2), "=r"(r3) : "r"(addr))

#define LDSM4T(r0,r1,r2,r3,addr) \
    asm volatile("ldmatrix.sync.aligned.m8n8.x4.trans.shared.b16 {%0,%1,%2,%3}, [%4];" \
        : "=r"(r0), "=r"(r1), "=r"(r2), "=r"(r3) : "r"(addr))

#define MMA16(dd, a0,a1,a2,a3, b0,b1) \
    asm volatile("mma.sync.aligned.m16n8k16.row.col.f32.f16.f16.f32 " \
        "{%0,%1,%2,%3}, {%4,%5,%6,%7}, {%8,%9}, {%0,%1,%2,%3};" \
        : "+f"((dd)[0]), "+f"((dd)[1]), "+f"((dd)[2]), "+f"((dd)[3]) \
        : "r"(a0), "r"(a1), "r"(a2), "r"(a3), "r"(b0), "r"(b1))

// ---------------- fp16 mma.sync GEMM ----------------------------------------
// C[M,N] = A[M,K] @ B[N,K]^T + bias (+GELU/+residual). CTA tile 128x128x64.
// 8 warps (256 thr), warp tile 64x32. 3 stages, 110.6KB smem -> 2 CTAs/SM.
// EPI: 0=bias, 1=bias+GELU, 2=bias+residual. OUTH: write half, else float.
#define PITCH_H 72
#define STAGE_BYTES (2*128*PITCH_H*2)        // 36864
#define NSTAGE 3
#define GEMM_SMEM (NSTAGE*STAGE_BYTES)       // 110592

template<int EPI, bool OUTH>
__global__ void __launch_bounds__(256, 2) gemm_f16(
    const __half* __restrict__ A, const __half* __restrict__ B,
    const float* __restrict__ bias, const float* __restrict__ res,
    void* __restrict__ Cv, int M, int N, int K)
{
    extern __shared__ char smem_dyn[];
    uint32_t sb = smem_u32(smem_dyn);
    int tid = threadIdx.x, wid = tid>>5, lane = tid&31;
    int bm = blockIdx.y*128, bn = blockIdx.x*128;
    int nc = K >> 6;                         // 64-wide K chunks

    const __half* gAr = A + (size_t)bm*K;
    const __half* gBr = B + (size_t)bn*K;

    int lrow = lane & 15;                    // ldmatrix row within 16
    int lcolh = (lane>>4)*8;                 // 8-half col offset
    int wm = (wid&1)*64, wn = (wid>>1)*32;

    float d[4][4][4];
    #pragma unroll
    for (int mi=0;mi<4;mi++)
        #pragma unroll
        for (int ni=0;ni<4;ni++)
            #pragma unroll
            for (int q=0;q<4;q++) d[mi][ni][q]=0.f;

    #define LOAD_CHUNK(s, c) do { \
        uint32_t aB = sb + (s)*STAGE_BYTES; \
        uint32_t bB = aB + 128*PITCH_H*2; \
        const __half* gA = gAr + (c)*64; \
        const __half* gB = gBr + (c)*64; \
        _Pragma("unroll") \
        for (int i=0;i<4;i++){ \
            int idx = tid + i*256; \
            int row = idx>>3, seg = idx&7; \
            uint32_t off = (uint32_t)(row*PITCH_H + seg*8)*2u; \
            int sz = (bm+row) < M ? 16 : 0; \
            asm volatile("cp.async.cg.shared.global [%0],[%1],16,%2;" \
                :: "r"(aB + off), "l"(gA + (size_t)row*K + seg*8), "r"(sz)); \
            asm volatile("cp.async.cg.shared.global [%0],[%1],16;" \
                :: "r"(bB + off), "l"(gB + (size_t)row*K + seg*8)); \
        } \
        asm volatile("cp.async.commit_group;"); } while(0)

    LOAD_CHUNK(0,0);
    LOAD_CHUNK(1,1);

    for (int c=0; c<nc; c++){
        int s = c % NSTAGE;
        asm volatile("cp.async.wait_group 1;");
        __syncthreads();
        if (c+2 < nc) LOAD_CHUNK((c+2)%NSTAGE, c+2);
        else asm volatile("cp.async.commit_group;");

        uint32_t sA = sb + s*STAGE_BYTES + (uint32_t)((wm+lrow)*PITCH_H + lcolh)*2u;
        uint32_t sB = sb + s*STAGE_BYTES + 128*PITCH_H*2 + (uint32_t)((wn+lrow)*PITCH_H + lcolh)*2u;
        #pragma unroll
        for (int kk=0;kk<4;kk++){
            uint32_t koff = kk*32;           // 16 halves
            uint32_t a[4][4];
            #pragma unroll
            for (int mi=0;mi<4;mi++)
                LDSM4(a[mi][0],a[mi][1],a[mi][2],a[mi][3], sA + mi*16*PITCH_H*2 + koff);
            uint32_t b[2][4];
            #pragma unroll
            for (int nj=0;nj<2;nj++)
                LDSM4(b[nj][0],b[nj][1],b[nj][2],b[nj][3], sB + nj*16*PITCH_H*2 + koff);
            #pragma unroll
            for (int mi=0;mi<4;mi++)
                #pragma unroll
                for (int ni=0;ni<4;ni++){
                    int nj = ni>>1, pr = ni&1;
                    MMA16(d[mi][ni], a[mi][0],a[mi][1],a[mi][2],a[mi][3],
                          b[nj][pr], b[nj][pr+2]);
                }
        }
    }

    __half* Ch = (__half*)Cv;
    float*  Cf = (float*)Cv;
    int rb = bm + wm + (lane>>2);
    int cb = bn + wn + (lane&3)*2;
    #pragma unroll
    for (int mi=0;mi<4;mi++){
        #pragma unroll
        for (int half=0; half<2; half++){
            int r = rb + mi*16 + half*8;
            if (r >= M) continue;
            const float* Rrow = (EPI==2) ? (res + (size_t)r*N) : (const float*)0;
            #pragma unroll
            for (int ni=0;ni<4;ni++){
                int cc = cb + ni*8;
                float v0 = d[mi][ni][half*2+0] + bias[cc];
                float v1 = d[mi][ni][half*2+1] + bias[cc+1];
                if (EPI==1){
                    v0 = 0.5f*v0*(1.f + erff(v0*0.70710678118654752f));
                    v1 = 0.5f*v1*(1.f + erff(v1*0.70710678118654752f));
                }
                if (EPI==2){ v0 += Rrow[cc]; v1 += Rrow[cc+1]; }
                if (OUTH)
                    *(__half2*)(Ch + (size_t)r*N + cc) = __floats2half2_rn(v0, v1);
                else
                    *(float2*)(Cf + (size_t)r*N + cc) = make_float2(v0, v1);
            }
        }
    }
}

// ---------------- fused weight float->half conversion ------------------------
#define CVT_N0 (3*EMB*EMB/4)
#define CVT_N1 (CVT_N0 + EMB*EMB/4)
#define CVT_N2 (CVT_N1 + HID*EMB/4)
#define CVT_N3 (CVT_N2 + EMB*HID/4)          // 1769472 float4 groups
__global__ void __launch_bounds__(256) cvt_all_kernel(
    const float* __restrict__ s0, __half* __restrict__ o0,
    const float* __restrict__ s1, __half* __restrict__ o1,
    const float* __restrict__ s2, __half* __restrict__ o2,
    const float* __restrict__ s3, __half* __restrict__ o3)
{
    int i = blockIdx.x*256 + threadIdx.x;
    const float4* src; __half2* dst; int off;
    if      (i < CVT_N0){ src=(const float4*)s0; dst=(__half2*)o0; off=i; }
    else if (i < CVT_N1){ src=(const float4*)s1; dst=(__half2*)o1; off=i-CVT_N0; }
    else if (i < CVT_N2){ src=(const float4*)s2; dst=(__half2*)o2; off=i-CVT_N1; }
    else                { src=(const float4*)s3; dst=(__half2*)o3; off=i-CVT_N2; }
    float4 v = src[off];
    dst[off*2+0] = __floats2half2_rn(v.x, v.y);
    dst[off*2+1] = __floats2half2_rn(v.z, v.w);
}

// ---------------- utils -----------------------------------------------------
__device__ __forceinline__ void lin7(int o, int& i0, int& i1, float& w0, float& w1) {
    int k = o >> 1;
    if (o & 1) { i0 = k; i1 = (k + 1 < 7) ? k + 1 : 6; w0 = 0.75f; w1 = 0.25f; }
    else       { i0 = (k - 1 >= 0) ? k - 1 : 0; i1 = k; w0 = 0.25f; w1 = 0.75f; }
}

// ---------------- LA pooling + channel MLP + fusion --------------------------
__global__ void __launch_bounds__(256) la_pool_kernel(
    const float* __restrict__ x,
    const float* __restrict__ f1_w, const float* __restrict__ f1_b,
    const float* __restrict__ f2_w, const float* __restrict__ f2_b,
    const float* __restrict__ v_w,  const float* __restrict__ v_b,
    float* __restrict__ fusion)
{
    int pw = blockIdx.x, ph = blockIdx.y, b = blockIdx.z;
    __shared__ float s_mean[LAH], s_max[LAH];
    int warp = threadIdx.x >> 5, lane = threadIdx.x & 31;

    for (int lh = warp; lh < LAH; lh += 8) {
        float sum = 0.f, mx = -1e30f;
        #pragma unroll
        for (int t = 0; t < 6; t++) {
            int idx = lane + 32 * t;
            int g  = idx % 48;
            int sp = idx / 48;
            int h = ph * 2 + (sp >> 1);
            int w = pw * 2 + (sp & 1);
            float v = x[((size_t)b * Ntok + 1 + h * 14 + w) * EMB + lh * 48 + g];
            sum += v; mx = fmaxf(mx, v);
        }
        #pragma unroll
        for (int o = 16; o > 0; o >>= 1) {
            sum += __shfl_xor_sync(0xffffffffu, sum, o);
            mx   = fmaxf(mx, __shfl_xor_sync(0xffffffffu, mx, o));
        }
        if (lane == 0) { s_mean[lh] = sum * (1.f / 192.f); s_max[lh] = mx; }
    }
    __syncthreads();

    if (threadIdx.x < LAH) {
        float hm = f1_b[0], hx = f1_b[0];
        #pragma unroll
        for (int lh = 0; lh < LAH; lh++) {
            hm = fmaf(s_mean[lh], f1_w[lh], hm);
            hx = fmaf(s_max[lh],  f1_w[lh], hx);
        }
        hm = fmaxf(hm, 0.f); hx = fmaxf(hx, 0.f);
        int lh = threadIdx.x;
        float m  = hm * f2_w[lh] + f2_b[lh];
        float mx = hx * f2_w[lh] + f2_b[lh];
        fusion[((size_t)b * LAH + lh) * 49 + ph * 7 + pw] =
            v_w[0] * m + v_w[1] * mx + v_b[0];
    }
}

// ---------------- LayerNorm: warp-per-token (8 tokens/CTA, no block barriers)
template<bool GATE>
__global__ void __launch_bounds__(256) ln_kernel(
    const float* __restrict__ x, const float* __restrict__ fusion,
    const float* __restrict__ gamma, const float* __restrict__ beta,
    __half* __restrict__ out)
{
    __shared__ float s_gate[8][LAH];
    int warp = threadIdx.x >> 5, lane = threadIdx.x & 31;
    int t = blockIdx.x * 8 + warp;           // MTOT = 12608 = 8*1576 exact
    int b = t / Ntok, n = t % Ntok;

    if (GATE) {
        if (lane < LAH) {
            float gv = 1.f;
            if (n > 0) {
                int hw = n - 1, oh = hw / 14, ow = hw % 14;
                int h0, h1, w0, w1; float ah0, ah1, aw0, aw1;
                lin7(oh, h0, h1, ah0, ah1);
                lin7(ow, w0, w1, aw0, aw1);
                const float* fp = fusion + ((size_t)b * LAH + lane) * 49;
                float val = ah0 * (aw0 * fp[h0 * 7 + w0] + aw1 * fp[h0 * 7 + w1])
                          + ah1 * (aw0 * fp[h1 * 7 + w0] + aw1 * fp[h1 * 7 + w1]);
                gv = 1.f + 1.f / (1.f + __expf(-val));
            }
            s_gate[warp][lane] = gv;
        }
        __syncwarp();
    }

    const float4* xp = (const float4*)(x + (size_t)t * EMB);
    float v[6][4];
    float sum = 0.f;
    #pragma unroll
    for (int i = 0; i < 6; i++) {
        float4 f = xp[lane + 32*i];
        float* ff = &f.x;
        #pragma unroll
        for (int q = 0; q < 4; q++) {
            float val = ff[q];
            if (GATE) {
                int c = (lane + 32*i)*4 + q;
                val *= s_gate[warp][c / 48];
            }
            v[i][q] = val; sum += val;
        }
    }
    #pragma unroll
    for (int o = 16; o > 0; o >>= 1) sum += __shfl_xor_sync(0xffffffffu, sum, o);
    float mean = sum * (1.f / (float)EMB);
    float vs = 0.f;
    #pragma unroll
    for (int i = 0; i < 6; i++)
        #pragma unroll
        for (int q = 0; q < 4; q++) { float d = v[i][q] - mean; vs += d * d; }
    #pragma unroll
    for (int o = 16; o > 0; o >>= 1) vs += __shfl_xor_sync(0xffffffffu, vs, o);
    float inv = rsqrtf(vs * (1.f / (float)EMB) + 1e-5f);

    half2x2* op = (half2x2*)(out + (size_t)t * EMB);
    const float4* gp = (const float4*)gamma;
    const float4* bp = (const float4*)beta;
    #pragma unroll
    for (int i = 0; i < 6; i++) {
        int e = lane + 32*i;
        float4 g = gp[e], bb = bp[e];
        half2x2 hv;
        hv.a = __floats2half2_rn((v[i][0]-mean)*inv*g.x + bb.x,
                                 (v[i][1]-mean)*inv*g.y + bb.y);
        hv.b = __floats2half2_rn((v[i][2]-mean)*inv*g.z + bb.z,
                                 (v[i][3]-mean)*inv*g.w + bb.w);
        op[e] = hv;
    }
}

// ---------------- fp16 tensor-core attention ---------------------------------
// grid (head=12, batch=64); 256 threads; 4 q-tiles per CTA; register softmax.
// V row-major + ldmatrix.trans O-phase; V load overlapped with first S-phase;
// pairwise named barriers between P-write and O-phase (P/red are pair-local).
// SMEM (bytes): K[224][72]h=32256, Q[64][72]h=9216, V[224][72]h=32256,
//               P[64][232]h=29696, red 1024  -> total 104448 (2 CTA/SM)
#define AT_K 0
#define AT_Q 32256
#define AT_V 41472
#define AT_P 73728
#define AT_R 103424
#define ATTN_SMEM (103424 + 1024)
#define VPITCH 232

__global__ void __launch_bounds__(256, 2) attn_mma(
    const __half* __restrict__ qkv, __half* __restrict__ o)
{
    extern __shared__ char smc[];
    uint32_t sbase = smem_u32(smc);
    uint32_t sK = sbase + AT_K;
    uint32_t sQ = sbase + AT_Q;
    uint32_t sV = sbase + AT_V;
    uint32_t sP = sbase + AT_P;
    __half* Pp = (__half*)(smc + AT_P);
    float* redm = (float*)(smc + AT_R);      // [2][64]
    float* reds = redm + 128;                // [2][64]

    int h = blockIdx.x, b = blockIdx.y;
    int tid = threadIdx.x, wid = tid>>5, lane = tid&31;
    size_t base = (size_t)b * Ntok * 2304 + (size_t)h * 64;

    #define LOAD_Q(qt) do { \
        _Pragma("unroll") \
        for (int i=0;i<2;i++){ \
            int idx = tid + i*256; \
            int row = idx >> 3, seg = idx & 7; \
            int tok = (qt)*64 + row; \
            int sz = (tok < Ntok) ? 16 : 0; \
            asm volatile("cp.async.cg.shared.global [%0],[%1],16,%2;" \
                :: "r"(sQ + (uint32_t)(row*PITCH_H + seg*8)*2u), \
                   "l"(qkv + base + (size_t)tok*2304 + seg*8), "r"(sz)); \
        } \
        asm volatile("cp.async.commit_group;"); } while(0)

    // group 0: K (224 rows x 8 segs of 16B; rows >= Ntok zero-filled)
    #pragma unroll
    for (int i=0;i<7;i++){
        int idx = tid + i*256;
        int row = idx >> 3, seg = idx & 7;
        int sz = (row < Ntok) ? 16 : 0;
        asm volatile("cp.async.cg.shared.global [%0],[%1],16,%2;"
            :: "r"(sK + (uint32_t)(row*PITCH_H + seg*8)*2u),
               "l"(qkv + base + (size_t)row*2304 + 768 + seg*8), "r"(sz));
    }
    asm volatile("cp.async.commit_group;");
    // group 1: Q tile 0
    LOAD_Q(0);
    // group 2: V (overlaps with first S-phase + softmax)
    #pragma unroll
    for (int i=0;i<7;i++){
        int idx = tid + i*256;
        int row = idx >> 3, seg = idx & 7;
        int sz = (row < Ntok) ? 16 : 0;
        asm volatile("cp.async.cg.shared.global [%0],[%1],16,%2;"
            :: "r"(sV + (uint32_t)(row*PITCH_H + seg*8)*2u),
               "l"(qkv + base + (size_t)row*2304 + 1536 + seg*8), "r"(sz));
    }
    asm volatile("cp.async.commit_group;");
    asm volatile("cp.async.wait_group 1;");  // K + Q ready; V still in flight
    __syncthreads();

    int lrow = lane & 15;
    int lcolh = (lane>>4)*8;
    int mt = wid & 3, nh = wid >> 2;
    int r1 = mt*16 + (lane>>2);              // fragment row (and +8)
    int cbase = nh*112 + (lane&3)*2;

    for (int qt=0; qt<4; qt++){
        if (qt > 0){
            asm volatile("cp.async.wait_group 0;");
            __syncthreads();
        }
        // ---- S = Q @ K^T : warp (mt,nh) -> rows mt*16+16, cols nh*112+112
        float sacc[14][4];
        #pragma unroll
        for (int t=0;t<14;t++)
            #pragma unroll
            for (int q=0;q<4;q++) sacc[t][q]=0.f;
        #pragma unroll
        for (int kk=0;kk<4;kk++){
            uint32_t koff = kk*32;
            uint32_t a0,a1,a2,a3;
            LDSM4(a0,a1,a2,a3, sQ + (uint32_t)((mt*16+lrow)*PITCH_H + lcolh)*2u + koff);
            #pragma unroll
            for (int njp=0;njp<7;njp++){
                uint32_t b0,b1,b2,b3;
                LDSM4(b0,b1,b2,b3,
                    sK + (uint32_t)((nh*112 + njp*16 + lrow)*PITCH_H + lcolh)*2u + koff);
                MMA16(sacc[njp*2+0], a0,a1,a2,a3, b0, b2);
                MMA16(sacc[njp*2+1], a0,a1,a2,a3, b1, b3);
            }
        }
        // ---- softmax: local max/sum, ONE cross-warp exchange, corr factor
        float mx1 = -1e30f, mx2 = -1e30f;
        #pragma unroll
        for (int t=0;t<14;t++){
            #pragma unroll
            for (int j=0;j<2;j++){
                int c = cbase + t*8 + j;
                float v1 = (c < Ntok) ? sacc[t][j]*0.125f   : -1e30f;
                float v2 = (c < Ntok) ? sacc[t][2+j]*0.125f : -1e30f;
                sacc[t][j] = v1; sacc[t][2+j] = v2;
                mx1 = fmaxf(mx1, v1); mx2 = fmaxf(mx2, v2);
            }
        }
        #pragma unroll
        for (int off=1; off<4; off<<=1){
            mx1 = fmaxf(mx1, __shfl_xor_sync(0xffffffffu, mx1, off));
            mx2 = fmaxf(mx2, __shfl_xor_sync(0xffffffffu, mx2, off));
        }
        float s1 = 0.f, s2 = 0.f;
        #pragma unroll
        for (int t=0;t<14;t++){
            #pragma unroll
            for (int j=0;j<2;j++){
                float e1 = __expf(sacc[t][j]   - mx1);
                float e2 = __expf(sacc[t][2+j] - mx2);
                sacc[t][j] = e1; sacc[t][2+j] = e2;
                s1 += e1; s2 += e2;
            }
        }
        #pragma unroll
        for (int off=1; off<4; off<<=1){
            s1 += __shfl_xor_sync(0xffffffffu, s1, off);
            s2 += __shfl_xor_sync(0xffffffffu, s2, off);
        }
        if ((lane&3)==0){
            redm[nh*64 + r1]   = mx1; redm[nh*64 + r1+8] = mx2;
            reds[nh*64 + r1]   = s1;  reds[nh*64 + r1+8] = s2;
        }
        __syncthreads();                      // full: also guards Q prefetch below
        float mA1 = redm[r1],   mB1 = redm[64+r1];
        float mg1 = fmaxf(mA1, mB1);
        float den1 = reds[r1]*__expf(mA1-mg1) + reds[64+r1]*__expf(mB1-mg1);
        float corr1 = __expf(mx1 - mg1) / den1;
        float mA2 = redm[r1+8], mB2 = redm[64+r1+8];
        float mg2 = fmaxf(mA2, mB2);
        float den2 = reds[r1+8]*__expf(mA2-mg2) + reds[64+r1+8]*__expf(mB2-mg2);
        float corr2 = __expf(mx2 - mg2) / den2;

        // prefetch next Q (all warps past S-phase after the full sync above)
        if (qt < 3) LOAD_Q(qt+1);

        #pragma unroll
        for (int t=0;t<14;t++){
            int c = cbase + t*8;
            *(__half2*)&Pp[r1*VPITCH + c]
                = __floats2half2_rn(sacc[t][0]*corr1, sacc[t][1]*corr1);
            *(__half2*)&Pp[(r1+8)*VPITCH + c]
                = __floats2half2_rn(sacc[t][2]*corr2, sacc[t][3]*corr2);
        }
        if (qt == 0){
            // V (group 2) must be complete; allow next-Q group to stay pending.
            asm volatile("cp.async.wait_group 1;");
            __syncthreads();                  // full: V visibility across all loaders
        } else {
            // P/red are pair-local: sync only warp pair {(mt,0),(mt,1)} = 64 thr
            asm volatile("bar.sync %0, 64;" :: "r"(1 + mt) : "memory");
        }

        // ---- O = P @ V : warp (mt,nh) -> rows mt*16+16, cols nh*32+32
        // B operand from row-major V via ldmatrix.trans
        float oacc[4][4];
        #pragma unroll
        for (int t=0;t<4;t++)
            #pragma unroll
            for (int q=0;q<4;q++) oacc[t][q]=0.f;
        #pragma unroll
        for (int k16=0;k16<14;k16++){
            uint32_t a0,a1,a2,a3;
            LDSM4(a0,a1,a2,a3, sP + (uint32_t)((mt*16+lrow)*VPITCH + lcolh)*2u + k16*32);
            #pragma unroll
            for (int nj=0;nj<2;nj++){
                uint32_t b0,b1,b2,b3;
                LDSM4T(b0,b1,b2,b3,
                    sV + (uint32_t)((k16*16 + lrow)*PITCH_H + nh*32 + nj*16 + lcolh)*2u);
                MMA16(oacc[nj*2+0], a0,a1,a2,a3, b0, b1);
                MMA16(oacc[nj*2+1], a0,a1,a2,a3, b2, b3);
            }
        }
        #pragma unroll
        for (int half=0; half<2; half++){
            int tok = qt*64 + r1 + half*8;
            if (tok < Ntok){
                __half* op = o + ((size_t)b*Ntok + tok)*EMB + h*64 + nh*32 + (lane&3)*2;
                #pragma unroll
                for (int t=0;t<4;t++)
                    *(__half2*)(op + t*8)
                        = __floats2half2_rn(oacc[t][half*2], oacc[t][half*2+1]);
            }
        }
    }
}

// ---------------- launch -----------------------------------------------------
extern "C" void kernel_launch(void* const* d_in, const int* in_sizes, int n_in,
                              void* d_out, int out_size)
{
    const float* x       = (const float*)d_in[0];
    const float* norm1_g = (const float*)d_in[1];
    const float* norm1_b = (const float*)d_in[2];
    const float* qkv_w   = (const float*)d_in[3];
    const float* qkv_b   = (const float*)d_in[4];
    const float* proj_w  = (const float*)d_in[5];
    const float* proj_b  = (const float*)d_in[6];
    const float* norm2_g = (const float*)d_in[7];
    const float* norm2_b = (const float*)d_in[8];
    const float* fc1_w   = (const float*)d_in[9];
    const float* fc1_b   = (const float*)d_in[10];
    const float* fc2_w   = (const float*)d_in[11];
    const float* fc2_b   = (const float*)d_in[12];
    const float* f1_w    = (const float*)d_in[13];
    const float* f1_b    = (const float*)d_in[14];
    const float* f2_w    = (const float*)d_in[15];
    const float* f2_b    = (const float*)d_in[16];
    const float* v_w     = (const float*)d_in[17];
    const float* v_b     = (const float*)d_in[18];
    float* out = (float*)d_out;

    float *fusion, *x1;
    __half *ln, *qkvb, *attno, *hbuf, *wq, *wp, *w1, *w2;
    cudaGetSymbolAddress((void**)&fusion, d_fusion);
    cudaGetSymbolAddress((void**)&x1,     d_x1);
    cudaGetSymbolAddress((void**)&ln,     hd_ln);
    cudaGetSymbolAddress((void**)&qkvb,   hd_qkv);
    cudaGetSymbolAddress((void**)&attno,  hd_att);
    cudaGetSymbolAddress((void**)&hbuf,   hd_h);
    cudaGetSymbolAddress((void**)&wq,     hd_wq);
    cudaGetSymbolAddress((void**)&wp,     hd_wp);
    cudaGetSymbolAddress((void**)&w1,     hd_w1);
    cudaGetSymbolAddress((void**)&w2,     hd_w2);

    cudaFuncSetAttribute(attn_mma, cudaFuncAttributeMaxDynamicSharedMemorySize, ATTN_SMEM);
    cudaFuncSetAttribute(gemm_f16<0,true >, cudaFuncAttributeMaxDynamicSharedMemorySize, GEMM_SMEM);
    cudaFuncSetAttribute(gemm_f16<1,true >, cudaFuncAttributeMaxDynamicSharedMemorySize, GEMM_SMEM);
    cudaFuncSetAttribute(gemm_f16<2,false>, cudaFuncAttributeMaxDynamicSharedMemorySize, GEMM_SMEM);

    // weights -> half copies (single fused launch)
    cvt_all_kernel<<<CVT_N3/256, 256>>>(qkv_w, wq, proj_w, wp, fc1_w, w1, fc2_w, w2);

    int mTiles = (MTOT + 127) / 128;   // 99

    // 1. LA pooling
    la_pool_kernel<<<dim3(7, 7, Bsz), 256>>>(x, f1_w, f1_b, f2_w, f2_b, v_w, v_b, fusion);
    // 2. LN1 (gate folded, warp-per-token) -> half
    ln_kernel<true><<<MTOT/8, 256>>>(x, fusion, norm1_g, norm1_b, ln);
    // 3. QKV GEMM (fp16 tensor) -> half
    gemm_f16<0,true><<<dim3(2304/128, mTiles), 256, GEMM_SMEM>>>(
        ln, wq, qkv_b, nullptr, qkvb, MTOT, 2304, EMB);
    // 4. fp16 tensor-core attention -> half
    attn_mma<<<dim3(NH, Bsz), 256, ATTN_SMEM>>>(qkvb, attno);
    // 5. proj GEMM + residual(x) -> float x1
    gemm_f16<2,false><<<dim3(EMB/128, mTiles), 256, GEMM_SMEM>>>(
        attno, wp, proj_b, x, x1, MTOT, EMB, EMB);
    // 6. LN2 (warp-per-token) -> half
    ln_kernel<false><<<MTOT/8, 256>>>(x1, nullptr, norm2_g, norm2_b, ln);
    // 7. fc1 GEMM + exact GELU -> half
    gemm_f16<1,true><<<dim3(HID/128, mTiles), 256, GEMM_SMEM>>>(
        ln, w1, fc1_b, nullptr, hbuf, MTOT, HID, EMB);
    // 8. fc2 GEMM + residual(x1) -> float out
    gemm_f16<2,false><<<dim3(EMB/128, mTiles), 256, GEMM_SMEM>>>(
        hbuf, w2, fc2_b, x1, out, MTOT, EMB, HID);
}